// round 15
// baseline (speedup 1.0000x reference)
#include <cuda_runtime.h>
#include <cuda_fp16.h>
#include <cstdint>

#define NJ 22
#define NF 8
#define SEQ 176
#define DM 256
#define HEADS 8
#define HD 32
#define BATCH 512
#define MROWS (BATCH*SEQ)   // 90112

typedef unsigned long long u64;

// Scratch: A=(x+pe) fp16, W fp16, QKV fp16
__device__ __half g_Af[(size_t)MROWS*DM];
__device__ __half g_Wf[768*DM];
__device__ __half g_qkv[3ULL*(size_t)MROWS*(size_t)DM];

// ---------------------------------------------------------------------------
// helpers
// ---------------------------------------------------------------------------
__device__ __forceinline__ uint32_t smem_u32(const void* p){
    uint32_t a;
    asm("{ .reg .u64 t; cvta.to.shared.u64 t, %1; cvt.u32.u64 %0, t; }" : "=r"(a) : "l"(p));
    return a;
}
__device__ __forceinline__ uint32_t sw64(uint32_t off){ return off ^ ((off >> 3) & 0x30); }

__device__ __forceinline__ void cpasync16(uint32_t dst, const void* src){
    asm volatile("cp.async.cg.shared.global [%0], [%1], 16;" :: "r"(dst), "l"(src) : "memory");
}
#define CPASYNC_COMMIT() asm volatile("cp.async.commit_group;" ::: "memory")
#define CPASYNC_WAIT(n)  asm volatile("cp.async.wait_group %0;" :: "n"(n) : "memory")

#define LDSM_X4(r0,r1,r2,r3,addr) \
    asm volatile("ldmatrix.sync.aligned.m8n8.x4.shared.b16 {%0,%1,%2,%3}, [%4];" \
        : "=r"(r0),"=r"(r1),"=r"(r2),"=r"(r3) : "r"(addr))
#define LDSM_X4_T(r0,r1,r2,r3,addr) \
    asm volatile("ldmatrix.sync.aligned.m8n8.x4.trans.shared.b16 {%0,%1,%2,%3}, [%4];" \
        : "=r"(r0),"=r"(r1),"=r"(r2),"=r"(r3) : "r"(addr))
#define MMAF16(d,a0,a1,a2,a3,b0,b1) \
    asm volatile("mma.sync.aligned.m16n8k16.row.col.f32.f16.f16.f32 " \
        "{%0,%1,%2,%3},{%4,%5,%6,%7},{%8,%9},{%0,%1,%2,%3};" \
        : "+f"((d)[0]),"+f"((d)[1]),"+f"((d)[2]),"+f"((d)[3]) \
        : "r"(a0),"r"(a1),"r"(a2),"r"(a3),"r"(b0),"r"(b1))

__device__ __forceinline__ uint32_t f22u(float x, float y){
    __half2 t = __floats2half2_rn(x, y);
    return *(uint32_t*)&t;
}

// ---------------------------------------------------------------------------
// Fused prep: W -> fp16 and (x + PE) -> fp16 (PE inline).
// ---------------------------------------------------------------------------
#define WN4 (768*DM/4)                 // 49152
#define AN4 (MROWS*DM/4)               // 5767168
#define PREP_BLOCKS ((WN4 + AN4)/256)  // 22720 exactly

__global__ __launch_bounds__(256) void prep_kernel(
    const float* __restrict__ x,
    const float* __restrict__ wq, const float* __restrict__ wk, const float* __restrict__ wv)
{
    int idx = blockIdx.x * 256 + threadIdx.x;
    if (idx < WN4) {
        int row = idx >> 6;
        const float* w = (row < 256) ? wq : (row < 512) ? wk : wv;
        int lrow = row & 255;
        int c4   = idx & 63;
        float4 v = *(const float4*)(w + (size_t)lrow*DM + c4*4);
        u64 hv = (u64)__half_as_ushort(__float2half(v.x))
               | ((u64)__half_as_ushort(__float2half(v.y)) << 16)
               | ((u64)__half_as_ushort(__float2half(v.z)) << 32)
               | ((u64)__half_as_ushort(__float2half(v.w)) << 48);
        *(u64*)(g_Wf + (size_t)idx*4) = hv;
    } else {
        int e4 = idx - WN4;
        int m  = e4 >> 6;
        int c4 = e4 & 63;
        float4 xa = *(const float4*)(x + (size_t)m*DM + c4*4);
        const float j = (float)(m % NJ);
        const float NEGLOG = -0.035977892078032f;   // -ln(10000)/256
        float e0 = __expf(NEGLOG * (float)(c4*4));
        float e1 = __expf(NEGLOG * (float)(c4*4 + 2));
        float s0, c0, s1, c1;
        __sincosf(j*e0, &s0, &c0);
        __sincosf(j*e1, &s1, &c1);
        u64 hv = (u64)__half_as_ushort(__float2half(xa.x + s0))
               | ((u64)__half_as_ushort(__float2half(xa.y + c0)) << 16)
               | ((u64)__half_as_ushort(__float2half(xa.z + s1)) << 32)
               | ((u64)__half_as_ushort(__float2half(xa.w + c1)) << 48);
        *(u64*)(g_Af + (size_t)e4*4) = hv;
    }
}

// ---------------------------------------------------------------------------
// QKV GEMM: plain fp16 mma.sync. CTA tile 128x128. KC=32, 3-stage cp.async.
// (unchanged best-known)
// ---------------------------------------------------------------------------
#define MT 128
#define NT 128
#define KC 32
#define NCHUNK (DM/KC)                 // 8
#define ARR8K 8192                     // 128 rows x 32 fp16
#define STAGE (2*ARR8K)                // Af, Bf = 16 KB
#define NSTAGE 3
#define GEMM_SMEM (NSTAGE*STAGE + 1024)

__device__ __forceinline__ void gemm_load_chunk(uint32_t uS, int m0, int n0,
                                                int cc, int ss, int tid)
{
    const uint32_t sb = uS + ss*STAGE;
#pragma unroll
    for (int j = 0; j < 4; j++) {
        int idx = j*256 + tid;         // 0..1023
        int arr = idx >> 9;            // 0=Af 1=Bf
        int w   = idx & 511;
        int r   = w >> 2;              // row 0..127
        int seg = w & 3;               // 16B segment
        uint32_t off = sw64((uint32_t)(r*64 + seg*16)) + arr*ARR8K;
        if (arr == 0) {
            cpasync16(sb + off, g_Af + (size_t)(m0 + r)*DM + cc*KC + seg*8);
        } else {
            cpasync16(sb + off, g_Wf + (size_t)(n0 + r)*DM + cc*KC + seg*8);
        }
    }
}

__global__ __launch_bounds__(256, 2) void qkv_mma_kernel(
    const float* __restrict__ bq, const float* __restrict__ bk, const float* __restrict__ bv)
{
    extern __shared__ char dyn_raw[];
    char* dsm = (char*)(((uintptr_t)dyn_raw + 1023) & ~(uintptr_t)1023);
    const uint32_t uS = smem_u32(dsm);

    const int tid  = threadIdx.x;
    const int wid  = tid >> 5;
    const int lane = tid & 31;
    const int wm   = wid & 3;
    const int wn   = wid >> 2;

    const int n0    = blockIdx.x * NT;
    const int m0    = blockIdx.y * MT;
    const int which = n0 >> 8;
    const int ncol0 = n0 & 255;
    const float* bbase = (which == 0) ? bq : (which == 1) ? bk : bv;

    const int a_row = wm*32 + (lane & 15);
    const int a_kb  = (lane >> 4) * 16;
    const int b_row = wn*64 + (lane & 7) + ((lane >> 4) & 1)*8;
    const int b_kb  = ((lane >> 3) & 1) * 16;

    float acc[2][8][4];
#pragma unroll
    for (int i = 0; i < 2; i++)
#pragma unroll
        for (int j = 0; j < 8; j++)
#pragma unroll
            for (int q = 0; q < 4; q++) acc[i][j][q] = 0.f;

    gemm_load_chunk(uS, m0, n0, 0, 0, tid);
    CPASYNC_COMMIT();
    gemm_load_chunk(uS, m0, n0, 1, 1, tid);
    CPASYNC_COMMIT();

    for (int c = 0; c < NCHUNK; c++) {
        if (c + 2 < NCHUNK) {
            CPASYNC_WAIT(1);
            __syncthreads();
            gemm_load_chunk(uS, m0, n0, c + 2, (c + 2) % NSTAGE, tid);
            CPASYNC_COMMIT();
        } else if (c + 1 < NCHUNK) {
            CPASYNC_WAIT(1);
            __syncthreads();
        } else {
            CPASYNC_WAIT(0);
            __syncthreads();
        }

        const uint32_t uAf = uS + (c % NSTAGE)*STAGE;
        const uint32_t uBf = uAf + ARR8K;

#pragma unroll
        for (int k = 0; k < 2; k++) {
            const int kb = k*32;
            uint32_t ao0 = sw64((uint32_t)( a_row      *64 + kb + a_kb));
            uint32_t ao1 = sw64((uint32_t)((a_row + 16)*64 + kb + a_kb));
            uint32_t a0[4], a1[4];
            LDSM_X4(a0[0],a0[1],a0[2],a0[3], uAf + ao0);
            LDSM_X4(a1[0],a1[1],a1[2],a1[3], uAf + ao1);
#pragma unroll
            for (int nt2 = 0; nt2 < 4; nt2++) {
                uint32_t bo = sw64((uint32_t)((b_row + nt2*16)*64 + kb + b_kb));
                uint32_t bf[4];
                LDSM_X4(bf[0], bf[1], bf[2], bf[3], uBf + bo);
                const int nt = nt2*2;
                MMAF16(acc[0][nt  ], a0[0],a0[1],a0[2],a0[3], bf[0],bf[1]);
                MMAF16(acc[1][nt  ], a1[0],a1[1],a1[2],a1[3], bf[0],bf[1]);
                MMAF16(acc[0][nt+1], a0[0],a0[1],a0[2],a0[3], bf[2],bf[3]);
                MMAF16(acc[1][nt+1], a1[0],a1[1],a1[2],a1[3], bf[2],bf[3]);
            }
        }
    }

    __half* obase = g_qkv + (size_t)which*MROWS*DM;
    const int mr = m0 + wm*32 + (lane >> 2);
    const int nc = ncol0 + wn*64 + (lane & 3)*2;
#pragma unroll
    for (int mt = 0; mt < 2; mt++) {
#pragma unroll
        for (int nt = 0; nt < 8; nt++) {
            const int col = nc + nt*8;
            const float b0 = bbase[col], b1 = bbase[col+1];
            __half2 h0 = __floats2half2_rn(acc[mt][nt][0] + b0, acc[mt][nt][1] + b1);
            __half2 h1 = __floats2half2_rn(acc[mt][nt][2] + b0, acc[mt][nt][3] + b1);
            *(__half2*)(obase + (size_t)(mr + mt*16    )*DM + col) = h0;
            *(__half2*)(obase + (size_t)(mr + mt*16 + 8)*DM + col) = h1;
        }
    }
}

// ---------------------------------------------------------------------------
// Tensor-core attention v2: Q/K/V staged in smem (coalesced), all fragments
// via ldmatrix. Tiles 32 x 40 halves (80B rows: 16B-aligned; 20-word stride
// -> each 8-row ldmatrix group hits 8 distinct banks). O reuses the Q tile.
// Block = (batch, frame), warp = head.
// ---------------------------------------------------------------------------
#define TS 40                                // tile stride in halves
#define HEAD_TILE (32*TS)                    // halves per tile
#define ATT_SMEM (HEADS*3*HEAD_TILE*2)       // 61440 B

__global__ __launch_bounds__(256) void attention_kernel(float* __restrict__ out)
{
    extern __shared__ __half smh[];
    const int bf   = blockIdx.x;
    const int b    = bf >> 3;
    const int f    = bf & 7;
    const int h    = threadIdx.x >> 5;
    const int lane = threadIdx.x & 31;
    const int g    = lane >> 2;          // fragment row group
    const int c    = lane & 3;           // fragment col group

    __half* qs = smh + h*(3*HEAD_TILE);          // Q, reused for O
    __half* ks = qs + HEAD_TILE;
    __half* vs = ks + HEAD_TILE;

    const size_t row0 = (size_t)b * SEQ + (size_t)f * NJ;
    const __half* Qb = g_qkv + row0*DM + h*HD;
    const __half* Kb = g_qkv + (size_t)MROWS*DM + row0*DM + h*HD;
    const __half* Vb = g_qkv + 2ULL*(size_t)MROWS*DM + row0*DM + h*HD;

    // ---- stage Q,K,V (coalesced 64B rows); zero pad rows 22..31 ----
#pragma unroll
    for (int kj = 0; kj < NJ; kj++) {
        const size_t src = (size_t)kj*DM + lane;
        qs[kj*TS + lane] = Qb[src];
        ks[kj*TS + lane] = Kb[src];
        vs[kj*TS + lane] = Vb[src];
    }
#pragma unroll
    for (int r = NJ; r < 32; r++) {
        qs[r*TS + lane] = __ushort_as_half(0);
        ks[r*TS + lane] = __ushort_as_half(0);
        vs[r*TS + lane] = __ushort_as_half(0);
    }
    __syncwarp();

    const uint32_t uQ = smem_u32(qs);
    const uint32_t uK = smem_u32(ks);
    const uint32_t uV = smem_u32(vs);

    // ---- Q A-fragments (both m-tiles upfront; frees qs for O) ----
    // addr rows (m*16 + lane&15), 16B half selected by lane>>4
    uint32_t qa[2][2][4];    // [m][kk][4]
    {
        const int arow = lane & 15;
        const int akb  = (lane >> 4) * 16;
#pragma unroll
        for (int m = 0; m < 2; m++)
#pragma unroll
            for (int kk = 0; kk < 2; kk++) {
                uint32_t addr = uQ + (uint32_t)((m*16 + arow)*TS)*2 + kk*32 + akb;
                LDSM_X4(qa[m][kk][0], qa[m][kk][1], qa[m][kk][2], qa[m][kk][3], addr);
            }
    }

    // ---- K B-fragments: kb[n][kk][2]; rows = keys, GEMM B lane mapping ----
    uint32_t kb[3][2][2];
    {
        const int brow = (lane & 7) + ((lane >> 4) & 1)*8;
        const int bkb  = ((lane >> 3) & 1) * 16;
#pragma unroll
        for (int rb = 0; rb < 2; rb++)          // row base 0, 16
#pragma unroll
            for (int kk = 0; kk < 2; kk++) {
                uint32_t addr = uK + (uint32_t)((rb*16 + brow)*TS)*2 + kk*32 + bkb;
                uint32_t t0, t1, t2, t3;
                LDSM_X4(t0, t1, t2, t3, addr);
                if (rb == 0) {
                    kb[0][kk][0] = t0; kb[0][kk][1] = t1;   // keys 0-7
                    kb[1][kk][0] = t2; kb[1][kk][1] = t3;   // keys 8-15
                } else {
                    kb[2][kk][0] = t0; kb[2][kk][1] = t1;   // keys 16-23
                }
            }
    }

    // ---- V^T B-fragments via ldmatrix.trans: vb[n(dims/8)][kk(keys/16)][2] ----
    uint32_t vb[4][2][2];
    {
        const int vrow = (lane & 7) + ((lane >> 3) & 1)*8;
        const int vcol = (lane >> 4)*8;
#pragma unroll
        for (int np = 0; np < 2; np++)
#pragma unroll
            for (int kk = 0; kk < 2; kk++) {
                uint32_t addr = uV + (uint32_t)((kk*16 + vrow)*TS + np*16 + vcol)*2;
                LDSM_X4_T(vb[2*np][kk][0], vb[2*np][kk][1],
                          vb[2*np+1][kk][0], vb[2*np+1][kk][1], addr);
            }
    }
    __syncwarp();   // all fragment reads done; qs tile free for O

    const uint32_t zero2 = 0;
    const float SC = 0.17677669529663687f;   // 1/sqrt(32)

#pragma unroll
    for (int m = 0; m < 2; m++) {
        // S = Q@K^T
        float s[3][4];
#pragma unroll
        for (int n = 0; n < 3; n++) {
            s[n][0] = s[n][1] = s[n][2] = s[n][3] = 0.f;
#pragma unroll
            for (int kk = 0; kk < 2; kk++)
                MMAF16(s[n], qa[m][kk][0],qa[m][kk][1],qa[m][kk][2],qa[m][kk][3],
                       kb[n][kk][0], kb[n][kk][1]);
        }
#pragma unroll
        for (int n = 0; n < 3; n++)
#pragma unroll
            for (int j = 0; j < 4; j++) s[n][j] *= SC;
        if (c == 3) { s[2][0] = s[2][1] = s[2][2] = s[2][3] = -1e30f; }

        // row max (row g -> [0],[1]; row g+8 -> [2],[3]) via 4-lane bfly
        float mxa = fmaxf(fmaxf(s[0][0], s[0][1]),
                    fmaxf(fmaxf(s[1][0], s[1][1]), fmaxf(s[2][0], s[2][1])));
        float mxb = fmaxf(fmaxf(s[0][2], s[0][3]),
                    fmaxf(fmaxf(s[1][2], s[1][3]), fmaxf(s[2][2], s[2][3])));
        mxa = fmaxf(mxa, __shfl_xor_sync(0xffffffffu, mxa, 1));
        mxa = fmaxf(mxa, __shfl_xor_sync(0xffffffffu, mxa, 2));
        mxb = fmaxf(mxb, __shfl_xor_sync(0xffffffffu, mxb, 1));
        mxb = fmaxf(mxb, __shfl_xor_sync(0xffffffffu, mxb, 2));

        float p[3][4];
        float sa = 0.f, sb = 0.f;
#pragma unroll
        for (int n = 0; n < 3; n++) {
            p[n][0] = __expf(s[n][0] - mxa);
            p[n][1] = __expf(s[n][1] - mxa);
            p[n][2] = __expf(s[n][2] - mxb);
            p[n][3] = __expf(s[n][3] - mxb);
            sa += p[n][0] + p[n][1];
            sb += p[n][2] + p[n][3];
        }
        sa += __shfl_xor_sync(0xffffffffu, sa, 1);
        sa += __shfl_xor_sync(0xffffffffu, sa, 2);
        sb += __shfl_xor_sync(0xffffffffu, sb, 1);
        sb += __shfl_xor_sync(0xffffffffu, sb, 2);
        const float inva = 1.f / sa;
        const float invb = 1.f / sb;

        // P fragments: C(m16n8) layout == A(m16k16) layout
        uint32_t pa0[4], pa1[2];
        pa0[0] = f22u(p[0][0], p[0][1]);
        pa0[1] = f22u(p[0][2], p[0][3]);
        pa0[2] = f22u(p[1][0], p[1][1]);
        pa0[3] = f22u(p[1][2], p[1][3]);
        pa1[0] = f22u(p[2][0], p[2][1]);
        pa1[1] = f22u(p[2][2], p[2][3]);

        // O = P@V
        float o[4][4];
#pragma unroll
        for (int n = 0; n < 4; n++) {
            o[n][0] = o[n][1] = o[n][2] = o[n][3] = 0.f;
            MMAF16(o[n], pa0[0], pa0[1], pa0[2], pa0[3], vb[n][0][0], vb[n][0][1]);
            MMAF16(o[n], pa1[0], pa1[1], zero2,  zero2,  vb[n][1][0], vb[n][1][1]);
        }

        // normalize + stage fp16 into the (reused) Q tile
        const int ra = m*16 + g, rb = ra + 8;
#pragma unroll
        for (int n = 0; n < 4; n++) {
            *(__half2*)(qs + ra*TS + 8*n + 2*c) = __floats2half2_rn(o[n][0]*inva, o[n][1]*inva);
            *(__half2*)(qs + rb*TS + 8*n + 2*c) = __floats2half2_rn(o[n][2]*invb, o[n][3]*invb);
        }
    }
    __syncwarp();

    // coalesced output
#pragma unroll
    for (int kj = 0; kj < NJ; kj++)
        out[(row0 + kj)*DM + h*HD + lane] = __half2float(qs[kj*TS + lane]);
}

// ---------------------------------------------------------------------------
extern "C" void kernel_launch(void* const* d_in, const int* in_sizes, int n_in,
                              void* d_out, int out_size)
{
    const float* x  = (const float*)d_in[0];
    const float* wq = (const float*)d_in[1];
    const float* bq = (const float*)d_in[2];
    const float* wk = (const float*)d_in[3];
    const float* bk = (const float*)d_in[4];
    const float* wv = (const float*)d_in[5];
    const float* bv = (const float*)d_in[6];
    float* out = (float*)d_out;

    cudaFuncSetAttribute(qkv_mma_kernel, cudaFuncAttributeMaxDynamicSharedMemorySize, GEMM_SMEM);
    cudaFuncSetAttribute(attention_kernel, cudaFuncAttributeMaxDynamicSharedMemorySize, ATT_SMEM);

    prep_kernel<<<PREP_BLOCKS, 256>>>(x, wq, wk, wv);

    dim3 ggrid(768 / NT, MROWS / MT);   // (6, 704); x-fastest shares A tile in L2
    qkv_mma_kernel<<<ggrid, 256, GEMM_SMEM>>>(bq, bk, bv);

    attention_kernel<<<BATCH * NF, 256, ATT_SMEM>>>(out);
}

// round 16
// speedup vs baseline: 1.3902x; 1.3902x over previous
#include <cuda_runtime.h>
#include <cuda_fp16.h>
#include <cstdint>

#define NJ 22
#define NF 8
#define SEQ 176
#define DM 256
#define HEADS 8
#define HD 32
#define BATCH 512
#define MROWS (BATCH*SEQ)   // 90112

typedef unsigned long long u64;

// Scratch: A=(x+pe) fp16, W fp16, QKV fp16
__device__ __half g_Af[(size_t)MROWS*DM];
__device__ __half g_Wf[768*DM];
__device__ __half g_qkv[3ULL*(size_t)MROWS*(size_t)DM];

// ---------------------------------------------------------------------------
// helpers
// ---------------------------------------------------------------------------
__device__ __forceinline__ uint32_t smem_u32(const void* p){
    uint32_t a;
    asm("{ .reg .u64 t; cvta.to.shared.u64 t, %1; cvt.u32.u64 %0, t; }" : "=r"(a) : "l"(p));
    return a;
}
__device__ __forceinline__ uint32_t sw64(uint32_t off){ return off ^ ((off >> 3) & 0x30); }

__device__ __forceinline__ void cpasync16(uint32_t dst, const void* src){
    asm volatile("cp.async.cg.shared.global [%0], [%1], 16;" :: "r"(dst), "l"(src) : "memory");
}
#define CPASYNC_COMMIT() asm volatile("cp.async.commit_group;" ::: "memory")
#define CPASYNC_WAIT(n)  asm volatile("cp.async.wait_group %0;" :: "n"(n) : "memory")

#define LDSM_X4(r0,r1,r2,r3,addr) \
    asm volatile("ldmatrix.sync.aligned.m8n8.x4.shared.b16 {%0,%1,%2,%3}, [%4];" \
        : "=r"(r0),"=r"(r1),"=r"(r2),"=r"(r3) : "r"(addr))
#define LDSM_X4_T(r0,r1,r2,r3,addr) \
    asm volatile("ldmatrix.sync.aligned.m8n8.x4.trans.shared.b16 {%0,%1,%2,%3}, [%4];" \
        : "=r"(r0),"=r"(r1),"=r"(r2),"=r"(r3) : "r"(addr))
#define MMAF16(d,a0,a1,a2,a3,b0,b1) \
    asm volatile("mma.sync.aligned.m16n8k16.row.col.f32.f16.f16.f32 " \
        "{%0,%1,%2,%3},{%4,%5,%6,%7},{%8,%9},{%0,%1,%2,%3};" \
        : "+f"((d)[0]),"+f"((d)[1]),"+f"((d)[2]),"+f"((d)[3]) \
        : "r"(a0),"r"(a1),"r"(a2),"r"(a3),"r"(b0),"r"(b1))

__device__ __forceinline__ uint32_t f22u(float x, float y){
    __half2 t = __floats2half2_rn(x, y);
    return *(uint32_t*)&t;
}

// ---------------------------------------------------------------------------
// Fused prep: W -> fp16 and (x + PE) -> fp16 (PE inline).
// ---------------------------------------------------------------------------
#define WN4 (768*DM/4)                 // 49152
#define AN4 (MROWS*DM/4)               // 5767168
#define PREP_BLOCKS ((WN4 + AN4)/256)  // 22720 exactly

__global__ __launch_bounds__(256) void prep_kernel(
    const float* __restrict__ x,
    const float* __restrict__ wq, const float* __restrict__ wk, const float* __restrict__ wv)
{
    int idx = blockIdx.x * 256 + threadIdx.x;
    if (idx < WN4) {
        int row = idx >> 6;
        const float* w = (row < 256) ? wq : (row < 512) ? wk : wv;
        int lrow = row & 255;
        int c4   = idx & 63;
        float4 v = *(const float4*)(w + (size_t)lrow*DM + c4*4);
        u64 hv = (u64)__half_as_ushort(__float2half(v.x))
               | ((u64)__half_as_ushort(__float2half(v.y)) << 16)
               | ((u64)__half_as_ushort(__float2half(v.z)) << 32)
               | ((u64)__half_as_ushort(__float2half(v.w)) << 48);
        *(u64*)(g_Wf + (size_t)idx*4) = hv;
    } else {
        int e4 = idx - WN4;
        int m  = e4 >> 6;
        int c4 = e4 & 63;
        float4 xa = *(const float4*)(x + (size_t)m*DM + c4*4);
        const float j = (float)(m % NJ);
        const float NEGLOG = -0.035977892078032f;   // -ln(10000)/256
        float e0 = __expf(NEGLOG * (float)(c4*4));
        float e1 = __expf(NEGLOG * (float)(c4*4 + 2));
        float s0, c0, s1, c1;
        __sincosf(j*e0, &s0, &c0);
        __sincosf(j*e1, &s1, &c1);
        u64 hv = (u64)__half_as_ushort(__float2half(xa.x + s0))
               | ((u64)__half_as_ushort(__float2half(xa.y + c0)) << 16)
               | ((u64)__half_as_ushort(__float2half(xa.z + s1)) << 32)
               | ((u64)__half_as_ushort(__float2half(xa.w + c1)) << 48);
        *(u64*)(g_Af + (size_t)e4*4) = hv;
    }
}

// ---------------------------------------------------------------------------
// QKV GEMM: plain fp16 mma.sync. CTA tile 128x128. KC=32, 4-stage cp.async
// pipeline (3 chunks in flight). Output stored as fp16.
// ---------------------------------------------------------------------------
#define MT 128
#define NT 128
#define KC 32
#define NCHUNK (DM/KC)                 // 8
#define ARR8K 8192                     // 128 rows x 32 fp16
#define STAGE (2*ARR8K)                // Af, Bf = 16 KB
#define NSTAGE 4
#define GEMM_SMEM (NSTAGE*STAGE + 1024)

__device__ __forceinline__ void gemm_load_chunk(uint32_t uS, int m0, int n0,
                                                int cc, int ss, int tid)
{
    const uint32_t sb = uS + ss*STAGE;
#pragma unroll
    for (int j = 0; j < 4; j++) {
        int idx = j*256 + tid;         // 0..1023
        int arr = idx >> 9;            // 0=Af 1=Bf
        int w   = idx & 511;
        int r   = w >> 2;              // row 0..127
        int seg = w & 3;               // 16B segment
        uint32_t off = sw64((uint32_t)(r*64 + seg*16)) + arr*ARR8K;
        if (arr == 0) {
            cpasync16(sb + off, g_Af + (size_t)(m0 + r)*DM + cc*KC + seg*8);
        } else {
            cpasync16(sb + off, g_Wf + (size_t)(n0 + r)*DM + cc*KC + seg*8);
        }
    }
}

__global__ __launch_bounds__(256, 2) void qkv_mma_kernel(
    const float* __restrict__ bq, const float* __restrict__ bk, const float* __restrict__ bv)
{
    extern __shared__ char dyn_raw[];
    char* dsm = (char*)(((uintptr_t)dyn_raw + 1023) & ~(uintptr_t)1023);
    const uint32_t uS = smem_u32(dsm);

    const int tid  = threadIdx.x;
    const int wid  = tid >> 5;
    const int lane = tid & 31;
    const int wm   = wid & 3;
    const int wn   = wid >> 2;

    const int n0    = blockIdx.x * NT;
    const int m0    = blockIdx.y * MT;
    const int which = n0 >> 8;
    const int ncol0 = n0 & 255;
    const float* bbase = (which == 0) ? bq : (which == 1) ? bk : bv;

    const int a_row = wm*32 + (lane & 15);
    const int a_kb  = (lane >> 4) * 16;
    const int b_row = wn*64 + (lane & 7) + ((lane >> 4) & 1)*8;
    const int b_kb  = ((lane >> 3) & 1) * 16;

    float acc[2][8][4];
#pragma unroll
    for (int i = 0; i < 2; i++)
#pragma unroll
        for (int j = 0; j < 8; j++)
#pragma unroll
            for (int q = 0; q < 4; q++) acc[i][j][q] = 0.f;

    // prologue: 3 chunks in flight
    gemm_load_chunk(uS, m0, n0, 0, 0, tid);
    CPASYNC_COMMIT();
    gemm_load_chunk(uS, m0, n0, 1, 1, tid);
    CPASYNC_COMMIT();
    gemm_load_chunk(uS, m0, n0, 2, 2, tid);
    CPASYNC_COMMIT();

    for (int c = 0; c < NCHUNK; c++) {
        if (c + 3 < NCHUNK) {
            CPASYNC_WAIT(2);               // chunk c landed (c+1, c+2 pending)
            __syncthreads();               // stage (c+3)%4 free (read at iter c-1)
            gemm_load_chunk(uS, m0, n0, c + 3, (c + 3) % NSTAGE, tid);
            CPASYNC_COMMIT();
        } else if (c + 2 < NCHUNK) {
            CPASYNC_WAIT(2);               // c=5: chunks 6,7 pending
            __syncthreads();
        } else if (c + 1 < NCHUNK) {
            CPASYNC_WAIT(1);               // c=6
            __syncthreads();
        } else {
            CPASYNC_WAIT(0);               // c=7
            __syncthreads();
        }

        const uint32_t uAf = uS + (c % NSTAGE)*STAGE;
        const uint32_t uBf = uAf + ARR8K;

#pragma unroll
        for (int k = 0; k < 2; k++) {
            const int kb = k*32;
            uint32_t ao0 = sw64((uint32_t)( a_row      *64 + kb + a_kb));
            uint32_t ao1 = sw64((uint32_t)((a_row + 16)*64 + kb + a_kb));
            uint32_t a0[4], a1[4];
            LDSM_X4(a0[0],a0[1],a0[2],a0[3], uAf + ao0);
            LDSM_X4(a1[0],a1[1],a1[2],a1[3], uAf + ao1);
#pragma unroll
            for (int nt2 = 0; nt2 < 4; nt2++) {
                uint32_t bo = sw64((uint32_t)((b_row + nt2*16)*64 + kb + b_kb));
                uint32_t bf[4];
                LDSM_X4(bf[0], bf[1], bf[2], bf[3], uBf + bo);
                const int nt = nt2*2;
                MMAF16(acc[0][nt  ], a0[0],a0[1],a0[2],a0[3], bf[0],bf[1]);
                MMAF16(acc[1][nt  ], a1[0],a1[1],a1[2],a1[3], bf[0],bf[1]);
                MMAF16(acc[0][nt+1], a0[0],a0[1],a0[2],a0[3], bf[2],bf[3]);
                MMAF16(acc[1][nt+1], a1[0],a1[1],a1[2],a1[3], bf[2],bf[3]);
            }
        }
    }

    // ---- epilogue: bias add + fp16 stores ----
    __half* obase = g_qkv + (size_t)which*MROWS*DM;
    const int mr = m0 + wm*32 + (lane >> 2);
    const int nc = ncol0 + wn*64 + (lane & 3)*2;
#pragma unroll
    for (int mt = 0; mt < 2; mt++) {
#pragma unroll
        for (int nt = 0; nt < 8; nt++) {
            const int col = nc + nt*8;
            const float b0 = bbase[col], b1 = bbase[col+1];
            __half2 h0 = __floats2half2_rn(acc[mt][nt][0] + b0, acc[mt][nt][1] + b1);
            __half2 h1 = __floats2half2_rn(acc[mt][nt][2] + b0, acc[mt][nt][3] + b1);
            *(__half2*)(obase + (size_t)(mr + mt*16    )*DM + col) = h0;
            *(__half2*)(obase + (size_t)(mr + mt*16 + 8)*DM + col) = h1;
        }
    }
}

// ---------------------------------------------------------------------------
// Tensor-core frame-local attention (round-14 proven version).
// Block = (batch, frame), warp = head. Q/K fragments direct from gmem,
// V via ldmatrix.trans from stride-72 smem tile, O staged fp16.
// ---------------------------------------------------------------------------
#define VT_STRIDE 72   // halves; 144B rows: 16B-aligned, 8-row bank-distinct
#define OS_STRIDE 34   // halves; 17-word rows, conflict-free
#define ATT_SMEM ((HEADS*32*VT_STRIDE + HEADS*32*OS_STRIDE)*2)   // 54272 B

__global__ __launch_bounds__(256, 2) void attention_kernel(float* __restrict__ out)
{
    extern __shared__ __half smh[];
    const int bf   = blockIdx.x;
    const int b    = bf >> 3;
    const int f    = bf & 7;
    const int h    = threadIdx.x >> 5;
    const int lane = threadIdx.x & 31;
    const int g    = lane >> 2;
    const int c    = lane & 3;

    __half* vt = smh + h*(32*VT_STRIDE);
    __half* os = smh + HEADS*(32*VT_STRIDE) + h*(32*OS_STRIDE);

    const size_t row0 = (size_t)b * SEQ + (size_t)f * NJ;
    const __half* Qb = g_qkv + row0*DM + h*HD;
    const __half* Kb = g_qkv + (size_t)MROWS*DM + row0*DM + h*HD;
    const __half* Vb = g_qkv + 2ULL*(size_t)MROWS*DM + row0*DM + h*HD;

#pragma unroll
    for (int kj = 0; kj < NJ; kj++)
        vt[kj*VT_STRIDE + lane] = Vb[(size_t)kj*DM + lane];
#pragma unroll
    for (int r = NJ; r < 32; r++)
        vt[r*VT_STRIDE + lane] = __ushort_as_half(0);
    __syncwarp();

    uint32_t kb[3][2][2];
#pragma unroll
    for (int n = 0; n < 3; n++)
#pragma unroll
        for (int kk = 0; kk < 2; kk++) {
            const __half* p = Kb + (size_t)(n*8 + g)*DM + kk*16 + 2*c;
            kb[n][kk][0] = *(const uint32_t*)p;
            kb[n][kk][1] = *(const uint32_t*)(p + 8);
        }

    uint32_t vb[4][2][2];
    {
        const uint32_t vtb = smem_u32(vt);
        const int vrow = (lane & 7) + ((lane >> 3) & 1)*8;
        const int vcol = (lane >> 4)*8;
#pragma unroll
        for (int np = 0; np < 2; np++)
#pragma unroll
            for (int kk = 0; kk < 2; kk++) {
                uint32_t addr = vtb + (uint32_t)((kk*16 + vrow)*VT_STRIDE + np*16 + vcol)*2;
                LDSM_X4_T(vb[2*np][kk][0], vb[2*np][kk][1],
                          vb[2*np+1][kk][0], vb[2*np+1][kk][1], addr);
            }
    }

    const uint32_t zero2 = 0;
    const float SC = 0.17677669529663687f;

#pragma unroll
    for (int m = 0; m < 2; m++) {
        uint32_t qa[2][4];
#pragma unroll
        for (int kk = 0; kk < 2; kk++) {
            const __half* p = Qb + (size_t)(m*16 + g)*DM + kk*16 + 2*c;
            qa[kk][0] = *(const uint32_t*)p;
            qa[kk][1] = *(const uint32_t*)(p + 8*DM);
            qa[kk][2] = *(const uint32_t*)(p + 8);
            qa[kk][3] = *(const uint32_t*)(p + 8*DM + 8);
        }

        float s[3][4];
#pragma unroll
        for (int n = 0; n < 3; n++) {
            s[n][0] = s[n][1] = s[n][2] = s[n][3] = 0.f;
#pragma unroll
            for (int kk = 0; kk < 2; kk++)
                MMAF16(s[n], qa[kk][0],qa[kk][1],qa[kk][2],qa[kk][3],
                       kb[n][kk][0], kb[n][kk][1]);
        }
#pragma unroll
        for (int n = 0; n < 3; n++)
#pragma unroll
            for (int j = 0; j < 4; j++) s[n][j] *= SC;
        if (c == 3) { s[2][0] = s[2][1] = s[2][2] = s[2][3] = -1e30f; }

        float mxa = fmaxf(fmaxf(s[0][0], s[0][1]),
                    fmaxf(fmaxf(s[1][0], s[1][1]), fmaxf(s[2][0], s[2][1])));
        float mxb = fmaxf(fmaxf(s[0][2], s[0][3]),
                    fmaxf(fmaxf(s[1][2], s[1][3]), fmaxf(s[2][2], s[2][3])));
        mxa = fmaxf(mxa, __shfl_xor_sync(0xffffffffu, mxa, 1));
        mxa = fmaxf(mxa, __shfl_xor_sync(0xffffffffu, mxa, 2));
        mxb = fmaxf(mxb, __shfl_xor_sync(0xffffffffu, mxb, 1));
        mxb = fmaxf(mxb, __shfl_xor_sync(0xffffffffu, mxb, 2));

        float p[3][4];
        float sa = 0.f, sb = 0.f;
#pragma unroll
        for (int n = 0; n < 3; n++) {
            p[n][0] = __expf(s[n][0] - mxa);
            p[n][1] = __expf(s[n][1] - mxa);
            p[n][2] = __expf(s[n][2] - mxb);
            p[n][3] = __expf(s[n][3] - mxb);
            sa += p[n][0] + p[n][1];
            sb += p[n][2] + p[n][3];
        }
        sa += __shfl_xor_sync(0xffffffffu, sa, 1);
        sa += __shfl_xor_sync(0xffffffffu, sa, 2);
        sb += __shfl_xor_sync(0xffffffffu, sb, 1);
        sb += __shfl_xor_sync(0xffffffffu, sb, 2);
        const float inva = 1.f / sa;
        const float invb = 1.f / sb;

        uint32_t pa0[4], pa1[2];
        pa0[0] = f22u(p[0][0], p[0][1]);
        pa0[1] = f22u(p[0][2], p[0][3]);
        pa0[2] = f22u(p[1][0], p[1][1]);
        pa0[3] = f22u(p[1][2], p[1][3]);
        pa1[0] = f22u(p[2][0], p[2][1]);
        pa1[1] = f22u(p[2][2], p[2][3]);

        float o[4][4];
#pragma unroll
        for (int n = 0; n < 4; n++) {
            o[n][0] = o[n][1] = o[n][2] = o[n][3] = 0.f;
            MMAF16(o[n], pa0[0], pa0[1], pa0[2], pa0[3], vb[n][0][0], vb[n][0][1]);
            MMAF16(o[n], pa1[0], pa1[1], zero2,  zero2,  vb[n][1][0], vb[n][1][1]);
        }

        const int ra = m*16 + g, rb = ra + 8;
#pragma unroll
        for (int n = 0; n < 4; n++) {
            *(__half2*)(os + ra*OS_STRIDE + 8*n + 2*c) = __floats2half2_rn(o[n][0]*inva, o[n][1]*inva);
            *(__half2*)(os + rb*OS_STRIDE + 8*n + 2*c) = __floats2half2_rn(o[n][2]*invb, o[n][3]*invb);
        }
    }
    __syncwarp();

#pragma unroll
    for (int kj = 0; kj < NJ; kj++)
        out[(row0 + kj)*DM + h*HD + lane] = __half2float(os[kj*OS_STRIDE + lane]);
}

// ---------------------------------------------------------------------------
extern "C" void kernel_launch(void* const* d_in, const int* in_sizes, int n_in,
                              void* d_out, int out_size)
{
    const float* x  = (const float*)d_in[0];
    const float* wq = (const float*)d_in[1];
    const float* bq = (const float*)d_in[2];
    const float* wk = (const float*)d_in[3];
    const float* bk = (const float*)d_in[4];
    const float* wv = (const float*)d_in[5];
    const float* bv = (const float*)d_in[6];
    float* out = (float*)d_out;

    cudaFuncSetAttribute(qkv_mma_kernel, cudaFuncAttributeMaxDynamicSharedMemorySize, GEMM_SMEM);
    cudaFuncSetAttribute(attention_kernel, cudaFuncAttributeMaxDynamicSharedMemorySize, ATT_SMEM);

    prep_kernel<<<PREP_BLOCKS, 256>>>(x, wq, wk, wv);

    dim3 ggrid(768 / NT, MROWS / MT);   // (6, 704); x-fastest shares A tile in L2
    qkv_mma_kernel<<<ggrid, 256, GEMM_SMEM>>>(bq, bk, bv);

    attention_kernel<<<BATCH * NF, 256, ATT_SMEM>>>(out);
}

// round 17
// speedup vs baseline: 1.4673x; 1.0555x over previous
#include <cuda_runtime.h>
#include <cuda_fp16.h>
#include <cstdint>

#define NJ 22
#define NF 8
#define SEQ 176
#define DM 256
#define HEADS 8
#define HD 32
#define BATCH 512
#define MROWS (BATCH*SEQ)   // 90112

typedef unsigned long long u64;

// Scratch: A=(x+pe) fp16, W fp16, QKV fp16 in head-major layout
// g_qkv index: ((which*HEADS + head)*MROWS + row)*32 + d
__device__ __half g_Af[(size_t)MROWS*DM];
__device__ __half g_Wf[768*DM];
__device__ __half g_qkv[3ULL*(size_t)MROWS*(size_t)DM];

// ---------------------------------------------------------------------------
// helpers
// ---------------------------------------------------------------------------
__device__ __forceinline__ uint32_t smem_u32(const void* p){
    uint32_t a;
    asm("{ .reg .u64 t; cvta.to.shared.u64 t, %1; cvt.u32.u64 %0, t; }" : "=r"(a) : "l"(p));
    return a;
}
__device__ __forceinline__ uint32_t sw64(uint32_t off){ return off ^ ((off >> 3) & 0x30); }

__device__ __forceinline__ void cpasync16(uint32_t dst, const void* src){
    asm volatile("cp.async.cg.shared.global [%0], [%1], 16;" :: "r"(dst), "l"(src) : "memory");
}
#define CPASYNC_COMMIT() asm volatile("cp.async.commit_group;" ::: "memory")
#define CPASYNC_WAIT(n)  asm volatile("cp.async.wait_group %0;" :: "n"(n) : "memory")

#define LDSM_X4(r0,r1,r2,r3,addr) \
    asm volatile("ldmatrix.sync.aligned.m8n8.x4.shared.b16 {%0,%1,%2,%3}, [%4];" \
        : "=r"(r0),"=r"(r1),"=r"(r2),"=r"(r3) : "r"(addr))
#define LDSM_X4_T(r0,r1,r2,r3,addr) \
    asm volatile("ldmatrix.sync.aligned.m8n8.x4.trans.shared.b16 {%0,%1,%2,%3}, [%4];" \
        : "=r"(r0),"=r"(r1),"=r"(r2),"=r"(r3) : "r"(addr))
#define MMAF16(d,a0,a1,a2,a3,b0,b1) \
    asm volatile("mma.sync.aligned.m16n8k16.row.col.f32.f16.f16.f32 " \
        "{%0,%1,%2,%3},{%4,%5,%6,%7},{%8,%9},{%0,%1,%2,%3};" \
        : "+f"((d)[0]),"+f"((d)[1]),"+f"((d)[2]),"+f"((d)[3]) \
        : "r"(a0),"r"(a1),"r"(a2),"r"(a3),"r"(b0),"r"(b1))

__device__ __forceinline__ uint32_t f22u(float x, float y){
    __half2 t = __floats2half2_rn(x, y);
    return *(uint32_t*)&t;
}

// ---------------------------------------------------------------------------
// Fused prep: W -> fp16 and (x + PE) -> fp16 (PE inline).
// ---------------------------------------------------------------------------
#define WN4 (768*DM/4)                 // 49152
#define AN4 (MROWS*DM/4)               // 5767168
#define PREP_BLOCKS ((WN4 + AN4)/256)  // 22720 exactly

__global__ __launch_bounds__(256) void prep_kernel(
    const float* __restrict__ x,
    const float* __restrict__ wq, const float* __restrict__ wk, const float* __restrict__ wv)
{
    int idx = blockIdx.x * 256 + threadIdx.x;
    if (idx < WN4) {
        int row = idx >> 6;
        const float* w = (row < 256) ? wq : (row < 512) ? wk : wv;
        int lrow = row & 255;
        int c4   = idx & 63;
        float4 v = *(const float4*)(w + (size_t)lrow*DM + c4*4);
        u64 hv = (u64)__half_as_ushort(__float2half(v.x))
               | ((u64)__half_as_ushort(__float2half(v.y)) << 16)
               | ((u64)__half_as_ushort(__float2half(v.z)) << 32)
               | ((u64)__half_as_ushort(__float2half(v.w)) << 48);
        *(u64*)(g_Wf + (size_t)idx*4) = hv;
    } else {
        int e4 = idx - WN4;
        int m  = e4 >> 6;
        int c4 = e4 & 63;
        float4 xa = *(const float4*)(x + (size_t)m*DM + c4*4);
        const float j = (float)(m % NJ);
        const float NEGLOG = -0.035977892078032f;   // -ln(10000)/256
        float e0 = __expf(NEGLOG * (float)(c4*4));
        float e1 = __expf(NEGLOG * (float)(c4*4 + 2));
        float s0, c0, s1, c1;
        __sincosf(j*e0, &s0, &c0);
        __sincosf(j*e1, &s1, &c1);
        u64 hv = (u64)__half_as_ushort(__float2half(xa.x + s0))
               | ((u64)__half_as_ushort(__float2half(xa.y + c0)) << 16)
               | ((u64)__half_as_ushort(__float2half(xa.z + s1)) << 32)
               | ((u64)__half_as_ushort(__float2half(xa.w + c1)) << 48);
        *(u64*)(g_Af + (size_t)e4*4) = hv;
    }
}

// ---------------------------------------------------------------------------
// QKV GEMM: plain fp16 mma.sync. CTA tile 128x128. KC=32, 4-stage cp.async
// pipeline. Output stored fp16 in head-major layout.
// ---------------------------------------------------------------------------
#define MT 128
#define NT 128
#define KC 32
#define NCHUNK (DM/KC)                 // 8
#define ARR8K 8192                     // 128 rows x 32 fp16
#define STAGE (2*ARR8K)                // Af, Bf = 16 KB
#define NSTAGE 4
#define GEMM_SMEM (NSTAGE*STAGE + 1024)

__device__ __forceinline__ void gemm_load_chunk(uint32_t uS, int m0, int n0,
                                                int cc, int ss, int tid)
{
    const uint32_t sb = uS + ss*STAGE;
#pragma unroll
    for (int j = 0; j < 4; j++) {
        int idx = j*256 + tid;         // 0..1023
        int arr = idx >> 9;            // 0=Af 1=Bf
        int w   = idx & 511;
        int r   = w >> 2;              // row 0..127
        int seg = w & 3;               // 16B segment
        uint32_t off = sw64((uint32_t)(r*64 + seg*16)) + arr*ARR8K;
        if (arr == 0) {
            cpasync16(sb + off, g_Af + (size_t)(m0 + r)*DM + cc*KC + seg*8);
        } else {
            cpasync16(sb + off, g_Wf + (size_t)(n0 + r)*DM + cc*KC + seg*8);
        }
    }
}

__global__ __launch_bounds__(256, 2) void qkv_mma_kernel(
    const float* __restrict__ bq, const float* __restrict__ bk, const float* __restrict__ bv)
{
    extern __shared__ char dyn_raw[];
    char* dsm = (char*)(((uintptr_t)dyn_raw + 1023) & ~(uintptr_t)1023);
    const uint32_t uS = smem_u32(dsm);

    const int tid  = threadIdx.x;
    const int wid  = tid >> 5;
    const int lane = tid & 31;
    const int wm   = wid & 3;
    const int wn   = wid >> 2;

    const int n0    = blockIdx.x * NT;
    const int m0    = blockIdx.y * MT;
    const int which = n0 >> 8;
    const int ncol0 = n0 & 255;
    const float* bbase = (which == 0) ? bq : (which == 1) ? bk : bv;

    const int a_row = wm*32 + (lane & 15);
    const int a_kb  = (lane >> 4) * 16;
    const int b_row = wn*64 + (lane & 7) + ((lane >> 4) & 1)*8;
    const int b_kb  = ((lane >> 3) & 1) * 16;

    float acc[2][8][4];
#pragma unroll
    for (int i = 0; i < 2; i++)
#pragma unroll
        for (int j = 0; j < 8; j++)
#pragma unroll
            for (int q = 0; q < 4; q++) acc[i][j][q] = 0.f;

    // prologue: 3 chunks in flight
    gemm_load_chunk(uS, m0, n0, 0, 0, tid);
    CPASYNC_COMMIT();
    gemm_load_chunk(uS, m0, n0, 1, 1, tid);
    CPASYNC_COMMIT();
    gemm_load_chunk(uS, m0, n0, 2, 2, tid);
    CPASYNC_COMMIT();

    for (int c = 0; c < NCHUNK; c++) {
        if (c + 3 < NCHUNK) {
            CPASYNC_WAIT(2);
            __syncthreads();
            gemm_load_chunk(uS, m0, n0, c + 3, (c + 3) % NSTAGE, tid);
            CPASYNC_COMMIT();
        } else if (c + 2 < NCHUNK) {
            CPASYNC_WAIT(2);
            __syncthreads();
        } else if (c + 1 < NCHUNK) {
            CPASYNC_WAIT(1);
            __syncthreads();
        } else {
            CPASYNC_WAIT(0);
            __syncthreads();
        }

        const uint32_t uAf = uS + (c % NSTAGE)*STAGE;
        const uint32_t uBf = uAf + ARR8K;

#pragma unroll
        for (int k = 0; k < 2; k++) {
            const int kb = k*32;
            uint32_t ao0 = sw64((uint32_t)( a_row      *64 + kb + a_kb));
            uint32_t ao1 = sw64((uint32_t)((a_row + 16)*64 + kb + a_kb));
            uint32_t a0[4], a1[4];
            LDSM_X4(a0[0],a0[1],a0[2],a0[3], uAf + ao0);
            LDSM_X4(a1[0],a1[1],a1[2],a1[3], uAf + ao1);
#pragma unroll
            for (int nt2 = 0; nt2 < 4; nt2++) {
                uint32_t bo = sw64((uint32_t)((b_row + nt2*16)*64 + kb + b_kb));
                uint32_t bf[4];
                LDSM_X4(bf[0], bf[1], bf[2], bf[3], uBf + bo);
                const int nt = nt2*2;
                MMAF16(acc[0][nt  ], a0[0],a0[1],a0[2],a0[3], bf[0],bf[1]);
                MMAF16(acc[1][nt  ], a1[0],a1[1],a1[2],a1[3], bf[0],bf[1]);
                MMAF16(acc[0][nt+1], a0[0],a0[1],a0[2],a0[3], bf[2],bf[3]);
                MMAF16(acc[1][nt+1], a1[0],a1[1],a1[2],a1[3], bf[2],bf[3]);
            }
        }
    }

    // ---- epilogue: bias add + fp16 stores, head-major layout ----
    const int mr = m0 + wm*32 + (lane >> 2);
    const int nc = ncol0 + wn*64 + (lane & 3)*2;
#pragma unroll
    for (int mt = 0; mt < 2; mt++) {
#pragma unroll
        for (int nt = 0; nt < 8; nt++) {
            const int col  = nc + nt*8;          // 0..255
            const int head = col >> 5;
            const int d    = col & 31;
            const float b0 = bbase[col], b1 = bbase[col+1];
            __half2 h0 = __floats2half2_rn(acc[mt][nt][0] + b0, acc[mt][nt][1] + b1);
            __half2 h1 = __floats2half2_rn(acc[mt][nt][2] + b0, acc[mt][nt][3] + b1);
            __half* hb = g_qkv + ((size_t)(which*HEADS + head)*MROWS)*32 + d;
            *(__half2*)(hb + (size_t)(mr + mt*16    )*32) = h0;
            *(__half2*)(hb + (size_t)(mr + mt*16 + 8)*32) = h1;
        }
    }
}

// ---------------------------------------------------------------------------
// Tensor-core frame-local attention (round-14 structure, head-major input).
// Per-(b,f,h) tiles are now 1408B contiguous: dense V staging, 64B-stride
// Q/K fragment loads. Block = (batch, frame), warp = head.
// ---------------------------------------------------------------------------
#define VT_STRIDE 72   // halves; 144B rows: 16B-aligned, 8-row bank-distinct
#define OS_STRIDE 34   // halves; 17-word rows, conflict-free
#define ATT_SMEM ((HEADS*32*VT_STRIDE + HEADS*32*OS_STRIDE)*2)   // 54272 B

__global__ __launch_bounds__(256, 2) void attention_kernel(float* __restrict__ out)
{
    extern __shared__ __half smh[];
    const int bf   = blockIdx.x;
    const int b    = bf >> 3;
    const int f    = bf & 7;
    const int h    = threadIdx.x >> 5;
    const int lane = threadIdx.x & 31;
    const int g    = lane >> 2;
    const int c    = lane & 3;

    __half* vt = smh + h*(32*VT_STRIDE);
    __half* os = smh + HEADS*(32*VT_STRIDE) + h*(32*OS_STRIDE);

    const size_t row0 = (size_t)b * SEQ + (size_t)f * NJ;
    // head-major: base of this head's rows, 32 halves per row
    const __half* Qb = g_qkv + ((size_t)(0*HEADS + h)*MROWS + row0)*32;
    const __half* Kb = g_qkv + ((size_t)(1*HEADS + h)*MROWS + row0)*32;
    const __half* Vb = g_qkv + ((size_t)(2*HEADS + h)*MROWS + row0)*32;

    // ---- stage V (contiguous 1408B block), zero pad rows 22-31 ----
#pragma unroll
    for (int kj = 0; kj < NJ; kj++)
        vt[kj*VT_STRIDE + lane] = Vb[kj*32 + lane];
#pragma unroll
    for (int r = NJ; r < 32; r++)
        vt[r*VT_STRIDE + lane] = __ushort_as_half(0);
    __syncwarp();

    // ---- K B-fragments direct from gmem (64B row stride now) ----
    uint32_t kb[3][2][2];
#pragma unroll
    for (int n = 0; n < 3; n++)
#pragma unroll
        for (int kk = 0; kk < 2; kk++) {
            const __half* p = Kb + (size_t)(n*8 + g)*32 + kk*16 + 2*c;
            kb[n][kk][0] = *(const uint32_t*)p;
            kb[n][kk][1] = *(const uint32_t*)(p + 8);
        }

    // ---- V^T B-fragments via ldmatrix.trans ----
    uint32_t vb[4][2][2];
    {
        const uint32_t vtb = smem_u32(vt);
        const int vrow = (lane & 7) + ((lane >> 3) & 1)*8;
        const int vcol = (lane >> 4)*8;
#pragma unroll
        for (int np = 0; np < 2; np++)
#pragma unroll
            for (int kk = 0; kk < 2; kk++) {
                uint32_t addr = vtb + (uint32_t)((kk*16 + vrow)*VT_STRIDE + np*16 + vcol)*2;
                LDSM_X4_T(vb[2*np][kk][0], vb[2*np][kk][1],
                          vb[2*np+1][kk][0], vb[2*np+1][kk][1], addr);
            }
    }

    const uint32_t zero2 = 0;
    const float SC = 0.17677669529663687f;   // 1/sqrt(32)

#pragma unroll
    for (int m = 0; m < 2; m++) {
        // Q A-fragments direct from gmem (rows m*16+g, +8)
        uint32_t qa[2][4];
#pragma unroll
        for (int kk = 0; kk < 2; kk++) {
            const __half* p = Qb + (size_t)(m*16 + g)*32 + kk*16 + 2*c;
            qa[kk][0] = *(const uint32_t*)p;
            qa[kk][1] = *(const uint32_t*)(p + 8*32);
            qa[kk][2] = *(const uint32_t*)(p + 8);
            qa[kk][3] = *(const uint32_t*)(p + 8*32 + 8);
        }

        float s[3][4];
#pragma unroll
        for (int n = 0; n < 3; n++) {
            s[n][0] = s[n][1] = s[n][2] = s[n][3] = 0.f;
#pragma unroll
            for (int kk = 0; kk < 2; kk++)
                MMAF16(s[n], qa[kk][0],qa[kk][1],qa[kk][2],qa[kk][3],
                       kb[n][kk][0], kb[n][kk][1]);
        }
#pragma unroll
        for (int n = 0; n < 3; n++)
#pragma unroll
            for (int j = 0; j < 4; j++) s[n][j] *= SC;
        if (c == 3) { s[2][0] = s[2][1] = s[2][2] = s[2][3] = -1e30f; }

        float mxa = fmaxf(fmaxf(s[0][0], s[0][1]),
                    fmaxf(fmaxf(s[1][0], s[1][1]), fmaxf(s[2][0], s[2][1])));
        float mxb = fmaxf(fmaxf(s[0][2], s[0][3]),
                    fmaxf(fmaxf(s[1][2], s[1][3]), fmaxf(s[2][2], s[2][3])));
        mxa = fmaxf(mxa, __shfl_xor_sync(0xffffffffu, mxa, 1));
        mxa = fmaxf(mxa, __shfl_xor_sync(0xffffffffu, mxa, 2));
        mxb = fmaxf(mxb, __shfl_xor_sync(0xffffffffu, mxb, 1));
        mxb = fmaxf(mxb, __shfl_xor_sync(0xffffffffu, mxb, 2));

        float p[3][4];
        float sa = 0.f, sb = 0.f;
#pragma unroll
        for (int n = 0; n < 3; n++) {
            p[n][0] = __expf(s[n][0] - mxa);
            p[n][1] = __expf(s[n][1] - mxa);
            p[n][2] = __expf(s[n][2] - mxb);
            p[n][3] = __expf(s[n][3] - mxb);
            sa += p[n][0] + p[n][1];
            sb += p[n][2] + p[n][3];
        }
        sa += __shfl_xor_sync(0xffffffffu, sa, 1);
        sa += __shfl_xor_sync(0xffffffffu, sa, 2);
        sb += __shfl_xor_sync(0xffffffffu, sb, 1);
        sb += __shfl_xor_sync(0xffffffffu, sb, 2);
        const float inva = 1.f / sa;
        const float invb = 1.f / sb;

        uint32_t pa0[4], pa1[2];
        pa0[0] = f22u(p[0][0], p[0][1]);
        pa0[1] = f22u(p[0][2], p[0][3]);
        pa0[2] = f22u(p[1][0], p[1][1]);
        pa0[3] = f22u(p[1][2], p[1][3]);
        pa1[0] = f22u(p[2][0], p[2][1]);
        pa1[1] = f22u(p[2][2], p[2][3]);

        float o[4][4];
#pragma unroll
        for (int n = 0; n < 4; n++) {
            o[n][0] = o[n][1] = o[n][2] = o[n][3] = 0.f;
            MMAF16(o[n], pa0[0], pa0[1], pa0[2], pa0[3], vb[n][0][0], vb[n][0][1]);
            MMAF16(o[n], pa1[0], pa1[1], zero2,  zero2,  vb[n][1][0], vb[n][1][1]);
        }

        const int ra = m*16 + g, rb = ra + 8;
#pragma unroll
        for (int n = 0; n < 4; n++) {
            *(__half2*)(os + ra*OS_STRIDE + 8*n + 2*c) = __floats2half2_rn(o[n][0]*inva, o[n][1]*inva);
            *(__half2*)(os + rb*OS_STRIDE + 8*n + 2*c) = __floats2half2_rn(o[n][2]*invb, o[n][3]*invb);
        }
    }
    __syncwarp();

    // coalesced output (original [row][256] layout)
#pragma unroll
    for (int kj = 0; kj < NJ; kj++)
        out[(row0 + kj)*DM + h*HD + lane] = __half2float(os[kj*OS_STRIDE + lane]);
}

// ---------------------------------------------------------------------------
extern "C" void kernel_launch(void* const* d_in, const int* in_sizes, int n_in,
                              void* d_out, int out_size)
{
    const float* x  = (const float*)d_in[0];
    const float* wq = (const float*)d_in[1];
    const float* bq = (const float*)d_in[2];
    const float* wk = (const float*)d_in[3];
    const float* bk = (const float*)d_in[4];
    const float* wv = (const float*)d_in[5];
    const float* bv = (const float*)d_in[6];
    float* out = (float*)d_out;

    cudaFuncSetAttribute(qkv_mma_kernel, cudaFuncAttributeMaxDynamicSharedMemorySize, GEMM_SMEM);
    cudaFuncSetAttribute(attention_kernel, cudaFuncAttributeMaxDynamicSharedMemorySize, ATT_SMEM);

    prep_kernel<<<PREP_BLOCKS, 256>>>(x, wq, wk, wv);

    dim3 ggrid(768 / NT, MROWS / MT);   // (6, 704); x-fastest shares A tile in L2
    qkv_mma_kernel<<<ggrid, 256, GEMM_SMEM>>>(bq, bk, bv);

    attention_kernel<<<BATCH * NF, 256, ATT_SMEM>>>(out);
}